// round 11
// baseline (speedup 1.0000x reference)
#include <cuda_runtime.h>
#include <cuda_fp16.h>
#include <float.h>
#include <stdint.h>

#define NMAX 4096
#define DIMK 256              // fp32 features per row
#define NSC  4                // 16KB sub-chunks per 128-row block (64 cols each)
#define NCH  4                // 64-kcol chunks per 128x128 tile
#define NSTG 3                // smem pipeline stages
#define NTHR 256
#define SUB_BYTES 16384       // one 128x64 fp16 sub-chunk, pre-swizzled

// ---------------- device scratch (no allocs allowed) ----------------
__device__ int   g_posmax[NMAX];                 // max d^2 over positives, float bits
__device__ int   g_negmin[NMAX];                 // min d^2 over negatives, float bits
__device__ float g_xx[NMAX];                     // squared norms (exact fp32)
__device__ int   g_lab[NMAX];                    // normalized labels
__device__ int   g_done;                         // CTA completion counter
// chunk-major pre-swizzled fp16 features:
// block b = row/128, sub-chunk c = col/64 -> contiguous 16KB at ((b*4+c)<<14)
__device__ __align__(16) __half g_f16s[NMAX * DIMK];

// ---------------- PTX helpers (sm_90-baseline ISA) ----------------
__device__ __forceinline__ uint32_t s2u(const void* p) {
    uint32_t a;
    asm("{ .reg .u64 t; cvta.to.shared.u64 t, %1; cvt.u32.u64 %0, t; }" : "=r"(a) : "l"(p));
    return a;
}
#define MBAR_INIT(a, c) asm volatile("mbarrier.init.shared.b64 [%0], %1;" :: "r"(a), "r"(c) : "memory")
#define MBAR_EXPECT_TX(a, b) asm volatile("mbarrier.arrive.expect_tx.shared.b64 _, [%0], %1;" :: "r"(a), "r"(b) : "memory")
#define MBAR_ARRIVE(a) asm volatile("mbarrier.arrive.release.cta.shared.b64 _, [%0];" :: "r"(a) : "memory")
#define FENCE_ASYNC()  asm volatile("fence.proxy.async.shared::cta;" ::: "memory")
__device__ __forceinline__ void mbar_wait(uint32_t mbar, uint32_t parity) {
    asm volatile(
        "{\n\t.reg .pred P;\n\t"
        "WL_%=:\n\t"
        "mbarrier.try_wait.parity.acquire.cta.shared::cta.b64 P, [%0], %1, 0x989680;\n\t"
        "@!P bra WL_%=;\n\t}"
        :: "r"(mbar), "r"(parity) : "memory");
}
__device__ __forceinline__ void bulk_g2s(uint32_t dst, const void* src, uint32_t mbar) {
    asm volatile(
        "cp.async.bulk.shared::cluster.global.mbarrier::complete_tx::bytes "
        "[%0], [%1], %2, [%3];"
        :: "r"(dst), "l"(src), "r"((uint32_t)SUB_BYTES), "r"(mbar) : "memory");
}
__device__ __forceinline__ void ldsm4(uint32_t* r, uint32_t a) {
    asm volatile("ldmatrix.sync.aligned.m8n8.x4.shared.b16 {%0,%1,%2,%3}, [%4];"
                 : "=r"(r[0]), "=r"(r[1]), "=r"(r[2]), "=r"(r[3]) : "r"(a));
}
__device__ __forceinline__ void mma16816(float* d, const uint32_t* a,
                                         uint32_t b0, uint32_t b1) {
    asm volatile(
        "mma.sync.aligned.m16n8k16.row.col.f32.f16.f16.f32 "
        "{%0,%1,%2,%3}, {%4,%5,%6,%7}, {%8,%9}, {%0,%1,%2,%3};"
        : "+f"(d[0]), "+f"(d[1]), "+f"(d[2]), "+f"(d[3])
        : "r"(a[0]), "r"(a[1]), "r"(a[2]), "r"(a[3]), "r"(b0), "r"(b1));
}
__device__ __forceinline__ int ldcg_i(const int* p) {
    int v; asm volatile("ld.global.cg.s32 %0, [%1];" : "=r"(v) : "l"(p)); return v;
}
#define SWZ(x) ((x) ^ ((((uint32_t)(x)) >> 3) & 0x70))

// SMEM layout (relative to 1024-aligned base)
#define SM_FULL   0           // 3 x 8B mbarriers
#define SM_EMPTY  64          // 3 x 8B mbarriers
#define SM_FLAG   128
#define SM_XXI    256         // 128 float
#define SM_LABI   768         // 128 int
#define SM_XXJ    1280        // 128 float
#define SM_LABJ   1792        // 128 int
#define SM_STAGE  4096        // 3 stages x 32KB: A(16K) | B(16K)
#define STAGE_SZ  32768
#define SMEM_TOTAL (SM_STAGE + NSTG * STAGE_SZ + 1024)   // ~101KB -> 2 CTAs/SM

// ---------------------------------------------------------------------------
// Prep: fp16 convert into chunk-major PRE-SWIZZLED layout, exact fp32 norms,
// label normalization, reduction + counter init. One warp per row.
// ---------------------------------------------------------------------------
__global__ void prep_kernel(const float* __restrict__ feat,
                            const int* __restrict__ lab_raw, int n) {
    int row  = blockIdx.x * 8 + (threadIdx.x >> 5);
    int lane = threadIdx.x & 31;
    if (row >= n) return;

    const float4* p = (const float4*)(feat + (size_t)row * DIMK);
    float4 v0 = p[2 * lane];
    float4 v1 = p[2 * lane + 1];

    float s = v0.x * v0.x + v0.y * v0.y + v0.z * v0.z + v0.w * v0.w
            + v1.x * v1.x + v1.y * v1.y + v1.z * v1.z + v1.w * v1.w;

    __half2 h0 = __floats2half2_rn(v0.x, v0.y);
    __half2 h1 = __floats2half2_rn(v0.z, v0.w);
    __half2 h2 = __floats2half2_rn(v1.x, v1.y);
    __half2 h3 = __floats2half2_rn(v1.z, v1.w);
    uint4 pk;
    pk.x = *(uint32_t*)&h0; pk.y = *(uint32_t*)&h1;
    pk.z = *(uint32_t*)&h2; pk.w = *(uint32_t*)&h3;

    const int blk = row >> 7;
    const int c   = lane >> 3;
    const uint32_t in_off = SWZ(((uint32_t)(row & 127)) * 128 + (lane & 7) * 16);
    char* dst = (char*)g_f16s + (((size_t)blk * NSC + c) << 14) + in_off;
    *(uint4*)dst = pk;

#pragma unroll
    for (int o = 16; o; o >>= 1) s += __shfl_xor_sync(0xffffffffu, s, o);

    if (lane == 0) {
        g_xx[row]     = s;
        g_posmax[row] = 0;
        g_negmin[row] = __float_as_int(FLT_MAX);
    }
    if (lane == 1) {
        bool is64 = true;
#pragma unroll
        for (int i = 0; i < 32; i++)
            if (lab_raw[2 * i + 1] != 0) { is64 = false; break; }
        g_lab[row] = is64 ? lab_raw[2 * row] : lab_raw[row];
    }
    if (row == 0 && lane == 2) g_done = 0;
}

// ---------------------------------------------------------------------------
__device__ __forceinline__ void decode_tile(int t, int ntb, int& bi, int& bj) {
    int ti = 0;
    while (t >= ntb - ti) { t -= ntb - ti; ti++; }
    bi = ti;
    bj = ti + t;
}

// Refill one 64-kcol chunk: A sub-chunk + B sub-chunk, two 16KB bulk copies.
__device__ __forceinline__ void issue_chunk(uint32_t st, uint32_t fb,
                                            int ti, int tj, int c) {
    MBAR_EXPECT_TX(fb, 2 * SUB_BYTES);
    const char* A = (const char*)g_f16s + ((((size_t)ti) * NSC + c) << 14);
    const char* B = (const char*)g_f16s + ((((size_t)tj) * NSC + c) << 14);
    bulk_g2s(st,             A, fb);
    bulk_g2s(st + SUB_BYTES, B, fb);
}

// MMA over one 64-kcol chunk, per-warp 32x64 output (fp16 single product).
__device__ __forceinline__ void mma_chunk(float acc[2][8][4], uint32_t st,
                                          int m_base, int n_base, int lane) {
    const uint32_t sA = st, sB = st + SUB_BYTES;
#pragma unroll
    for (int ks = 0; ks < 4; ks++) {
        const uint32_t koff = (uint32_t)ks * 32 + ((lane >> 4) << 4);
        uint32_t a[2][4], b[4][4];
#pragma unroll
        for (int mt = 0; mt < 2; mt++) {
            uint32_t ad = SWZ((uint32_t)(m_base + mt * 16 + (lane & 15)) * 128 + koff);
            ldsm4(a[mt], sA + ad);
        }
#pragma unroll
        for (int p = 0; p < 4; p++) {
            uint32_t bd = SWZ((uint32_t)(n_base + p * 16 + (lane & 15)) * 128 + koff);
            ldsm4(b[p], sB + bd);
        }
#pragma unroll
        for (int mt = 0; mt < 2; mt++)
#pragma unroll
            for (int nt = 0; nt < 8; nt++) {
                const int p = nt >> 1, q = nt & 1;
                mma16816(acc[mt][nt], a[mt], b[p][q], b[p][2 + q]);
            }
    }
}

// ---------------------------------------------------------------------------
// Persistent kernel: 2 CTAs/SM, 128x128 tiles, 3-stage 32KB ring,
// early producer, smem-staged epilogue operands, fused final reduction.
// ---------------------------------------------------------------------------
__global__ void __launch_bounds__(NTHR, 2) tile_kernel(float* __restrict__ out, int n) {
    extern __shared__ char smem_raw[];
    uint32_t sb_raw = s2u(smem_raw);
    uint32_t pad = (1024u - (sb_raw & 1023u)) & 1023u;
    char* sm = smem_raw + pad;
    uint32_t sb = sb_raw + pad;

    float* xxi_s  = (float*)(sm + SM_XXI);
    int*   labi_s = (int*)(sm + SM_LABI);
    float* xxj_s  = (float*)(sm + SM_XXJ);
    int*   labj_s = (int*)(sm + SM_LABJ);

    const int tid = threadIdx.x, lane = tid & 31, w = tid >> 5;
    const int m_base = (w & 3) * 32;     // 4 warps along M (128 rows)
    const int n_base = (w >> 2) * 64;    // 2 warps along N (128 cols)

    const int ntb = n >> 7;
    const int T   = ntb * (ntb + 1) / 2;          // 528 triangle tiles
    const int myT = (T - (int)blockIdx.x + (int)gridDim.x - 1) / (int)gridDim.x;
    const int G   = myT * NCH;                    // chunks this CTA streams

    if (tid == 0) {
#pragma unroll
        for (int s = 0; s < NSTG; s++) {
            MBAR_INIT(sb + SM_FULL + s * 8, 1);
            MBAR_INIT(sb + SM_EMPTY + s * 8, 8);
        }
    }
    __syncthreads();

    if (G > 0) {
        int ti0, tj0;
        decode_tile(blockIdx.x, ntb, ti0, tj0);
        if (tid == 0) {
#pragma unroll
            for (int c = 0; c < NSTG; c++)
                if (c < G)
                    issue_chunk(sb + SM_STAGE + c * STAGE_SZ,
                                sb + SM_FULL + c * 8, ti0, tj0, c);
        }

        float acc[2][8][4];
        int ti = ti0, tj = tj0;

        for (int g = 0; g < G; g++) {
            const int s = g % NSTG;
            const uint32_t fpar = (uint32_t)((g / NSTG) & 1);

            if ((g & 3) == 0) {
                if (g > 0) decode_tile((int)blockIdx.x + (g >> 2) * (int)gridDim.x,
                                       ntb, ti, tj);
                __syncthreads();                   // prev epilogue done reading
                if (tid < 128) {
                    xxi_s[tid]  = g_xx[ti * 128 + tid];
                    labi_s[tid] = g_lab[ti * 128 + tid];
                } else {
                    int q = tid - 128;
                    xxj_s[q]  = g_xx[tj * 128 + q];
                    labj_s[q] = g_lab[tj * 128 + q];
                }
                __syncthreads();
#pragma unroll
                for (int a = 0; a < 2; a++)
#pragma unroll
                    for (int b = 0; b < 8; b++)
#pragma unroll
                        for (int e = 0; e < 4; e++) acc[a][b][e] = 0.f;
            }

            // early producer: refill chunk g+NSTG before this chunk's full-wait
            if (tid == 0 && g >= 1) {
                const int cl = g + NSTG - 1;      // stage released at chunk g-1
                if (cl < G) {
                    const int s2 = cl % NSTG;
                    mbar_wait(sb + SM_EMPTY + s2 * 8, (uint32_t)(((cl / NSTG) - 1) & 1));
                    FENCE_ASYNC();
                    int lti, ltj;
                    decode_tile((int)blockIdx.x + (cl >> 2) * (int)gridDim.x,
                                ntb, lti, ltj);
                    issue_chunk(sb + SM_STAGE + s2 * STAGE_SZ,
                                sb + SM_FULL + s2 * 8, lti, ltj, cl & 3);
                }
            }

            mbar_wait(sb + SM_FULL + s * 8, fpar);
            mma_chunk(acc, sb + SM_STAGE + s * STAGE_SZ, m_base, n_base, lane);
            if (lane == 0) MBAR_ARRIVE(sb + SM_EMPTY + s * 8);

            if ((g & 3) == 3) {
                // ---- epilogue over this warp's 32x64 block ----
                float xi[4]; int li[4];
#pragma unroll
                for (int mt = 0; mt < 2; mt++)
#pragma unroll
                    for (int rh = 0; rh < 2; rh++) {
                        int r = m_base + mt * 16 + (lane >> 2) + 8 * rh;
                        xi[mt * 2 + rh] = xxi_s[r];
                        li[mt * 2 + rh] = labi_s[r];
                    }
                float xj[16]; int lj[16];
#pragma unroll
                for (int nt = 0; nt < 8; nt++)
#pragma unroll
                    for (int cc = 0; cc < 2; cc++) {
                        int q = n_base + nt * 8 + (lane & 3) * 2 + cc;
                        xj[nt * 2 + cc] = xxj_s[q];
                        lj[nt * 2 + cc] = labj_s[q];
                    }
#pragma unroll
                for (int mt = 0; mt < 2; mt++)
#pragma unroll
                    for (int nt = 0; nt < 8; nt++)
#pragma unroll
                        for (int e = 0; e < 4; e++) {
                            int rh = e >> 1, cc = e & 1;
                            acc[mt][nt][e] = fmaf(-2.f, acc[mt][nt][e],
                                                  xi[mt * 2 + rh] + xj[nt * 2 + cc]);
                        }

                // row direction
#pragma unroll
                for (int mt = 0; mt < 2; mt++)
#pragma unroll
                    for (int rh = 0; rh < 2; rh++) {
                        float pm = -1.f, nm = FLT_MAX;
                        const int L = li[mt * 2 + rh];
#pragma unroll
                        for (int nt = 0; nt < 8; nt++)
#pragma unroll
                            for (int cc = 0; cc < 2; cc++) {
                                float v = acc[mt][nt][rh * 2 + cc];
                                if (L == lj[nt * 2 + cc]) pm = fmaxf(pm, v);
                                else                      nm = fminf(nm, v);
                            }
                        pm = fmaxf(pm, __shfl_xor_sync(0xffffffffu, pm, 1));
                        pm = fmaxf(pm, __shfl_xor_sync(0xffffffffu, pm, 2));
                        nm = fminf(nm, __shfl_xor_sync(0xffffffffu, nm, 1));
                        nm = fminf(nm, __shfl_xor_sync(0xffffffffu, nm, 2));
                        if ((lane & 3) == 0) {
                            int gi = ti * 128 + m_base + mt * 16 + (lane >> 2) + 8 * rh;
                            atomicMax(&g_posmax[gi], __float_as_int(pm));
                            atomicMin(&g_negmin[gi], __float_as_int(nm));
                        }
                    }

                // column direction (symmetry)
#pragma unroll
                for (int nt = 0; nt < 8; nt++)
#pragma unroll
                    for (int cc = 0; cc < 2; cc++) {
                        float pm = -1.f, nm = FLT_MAX;
                        const int L = lj[nt * 2 + cc];
#pragma unroll
                        for (int mt = 0; mt < 2; mt++)
#pragma unroll
                            for (int rh = 0; rh < 2; rh++) {
                                float v = acc[mt][nt][rh * 2 + cc];
                                if (L == li[mt * 2 + rh]) pm = fmaxf(pm, v);
                                else                      nm = fminf(nm, v);
                            }
                        pm = fmaxf(pm, __shfl_xor_sync(0xffffffffu, pm, 4));
                        pm = fmaxf(pm, __shfl_xor_sync(0xffffffffu, pm, 8));
                        pm = fmaxf(pm, __shfl_xor_sync(0xffffffffu, pm, 16));
                        nm = fminf(nm, __shfl_xor_sync(0xffffffffu, nm, 4));
                        nm = fminf(nm, __shfl_xor_sync(0xffffffffu, nm, 8));
                        nm = fminf(nm, __shfl_xor_sync(0xffffffffu, nm, 16));
                        if (lane < 4) {
                            int gj = tj * 128 + n_base + nt * 8 + (lane & 3) * 2 + cc;
                            atomicMax(&g_posmax[gj], __float_as_int(pm));
                            atomicMin(&g_negmin[gj], __float_as_int(nm));
                        }
                    }
            }
        }
    }

    // ---- completion counter: last CTA performs the finalize reduction ----
    __syncthreads();
    if (tid == 0) {
        __threadfence();
        int prev = atomicAdd(&g_done, 1);
        *(volatile int*)(sm + SM_FLAG) = (prev == (int)gridDim.x - 1) ? 1 : 0;
    }
    __syncthreads();
    if (*(volatile int*)(sm + SM_FLAG)) {
        float* ss = (float*)(sm + SM_STAGE);
        float* sc = ss + NTHR;
        float sum = 0.f, cnt = 0.f;
        for (int i = tid; i < n; i += NTHR) {
            float ap2 = __int_as_float(ldcg_i(&g_posmax[i]));
            float ap  = sqrtf(fmaxf(ap2, 1e-12f));
            float nm2 = __int_as_float(ldcg_i(&g_negmin[i]));
            bool  has_neg = nm2 < 1e30f;
            float an  = has_neg ? sqrtf(fmaxf(nm2, 1e-12f)) : 0.f;
            bool  valid = (ap < 1000000.0f) && (an > 0.f);
            if (valid) {
                sum += fmaxf(0.3f + ap - an, 0.f);
                cnt += 1.f;
            }
        }
        ss[tid] = sum;
        sc[tid] = cnt;
        __syncthreads();
        for (int o = NTHR / 2; o; o >>= 1) {
            if (tid < o) {
                ss[tid] += ss[tid + o];
                sc[tid] += sc[tid + o];
            }
            __syncthreads();
        }
        if (tid == 0)
            out[0] = (sc[0] > 0.f) ? ss[0] / fmaxf(sc[0], 1.f) : 0.f;
    }
}

// ---------------------------------------------------------------------------
extern "C" void kernel_launch(void* const* d_in, const int* in_sizes, int n_in,
                              void* d_out, int out_size) {
    const float* feat   = (const float*)d_in[0];
    const int*   labels = (const int*)d_in[1];   // int32/int64 auto-detected
    int n = in_sizes[1];                         // 4096

    cudaFuncSetAttribute(tile_kernel, cudaFuncAttributeMaxDynamicSharedMemorySize,
                         SMEM_TOTAL);

    prep_kernel<<<(n + 7) / 8, 256>>>(feat, labels, n);
    tile_kernel<<<296, NTHR, SMEM_TOTAL>>>((float*)d_out, n);
}